// round 10
// baseline (speedup 1.0000x reference)
#include <cuda_runtime.h>
#include <cuda_fp8.h>
#include <cstdint>

// ---------------------------------------------------------------------------
// Problem constants
// ---------------------------------------------------------------------------
#define B_ROWS  16384
#define D_DIM   784
#define C_DIM   2048
#define OUT_DIM 10

#define KPAD   800               // 784 padded to 25*32 (fp8 bytes)
#define KWORDS 200               // KPAD/4
#define KB     160               // K bytes per pipeline block
#define NKBLK  5                 // blocks per chunk (5*160 = 800)
#define NK32   5                 // k32 steps per block
#define TM     128               // x rows per unit
#define TN     128               // centres per chunk
#define NSLICE 8                 // C split across units
#define CHPS   2                 // chunks per unit (256 centres)
#define BPU    (CHPS * NKBLK)    // 10 blocks per unit
#define NUNITS ((B_ROWS / TM) * NSLICE)   // 1024 work units
#define NMTILE (B_ROWS / TM)     // 128
#define NTHREADS 256

// smem tile stride: 160 data + 16 pad bytes (ldmatrix phases r*11 mod 8 distinct)
#define ASTB  176
#define TILEB 22528u             // 128 * 176
#define NSTAGE 3
#define WST   12                 // floats per Wcol row (10 + 2 pad)

// smem byte offsets
#define OFF_A    0u                       // 3 x 22528 = 67584
#define OFF_B    67584u                   // 3 x 22528 = 67584
#define OFF_WCOL 135168u                  // 128 x 12 x 4 = 6144
#define OFF_C2   141312u                  // 128 x 4
#define OFF_IS2  141824u
#define OFF_RED  142336u                  // 128 x 12 x 4 = 6144
#define SMEM_TOTAL 148480u

// ---------------------------------------------------------------------------
// Device-global scratch (no allocations allowed)
// ---------------------------------------------------------------------------
__device__ __align__(16) uint32_t g_xq[(size_t)B_ROWS * KWORDS];   // 13.1 MB fp8
__device__ __align__(16) uint32_t g_cq[(size_t)C_DIM * KWORDS];    // 1.6 MB fp8
__device__ float g_x2[B_ROWS];
__device__ float g_c2[C_DIM];
__device__ float g_is2[C_DIM];
__device__ __align__(16) float g_part[(size_t)NSLICE * B_ROWS * OUT_DIM]; // 5.2 MB
__device__ int g_cnt[NMTILE];    // per-m-tile slice completion counters

// ---------------------------------------------------------------------------
// PTX helpers (base-ISA sm_80/89 era; valid for compute_103 virtual arch)
// ---------------------------------------------------------------------------
__device__ __forceinline__ uint32_t smem_u32(const void* p) {
    uint32_t a;
    asm("{ .reg .u64 t; cvta.to.shared.u64 t, %1; cvt.u32.u64 %0, t; }" : "=r"(a) : "l"(p));
    return a;
}

__device__ __forceinline__ void cp16(uint32_t dst, const void* src) {
    asm volatile("cp.async.cg.shared.global [%0], [%1], 16;" :: "r"(dst), "l"(src));
}
#define CP_COMMIT() asm volatile("cp.async.commit_group;" ::: "memory")
#define CP_WAIT0()  asm volatile("cp.async.wait_group 0;"  ::: "memory")
#define CP_WAIT1()  asm volatile("cp.async.wait_group 1;"  ::: "memory")

__device__ __forceinline__ void ldm_x4(uint32_t* r, uint32_t addr) {
    asm volatile("ldmatrix.sync.aligned.m8n8.x4.shared.b16 {%0,%1,%2,%3}, [%4];"
                 : "=r"(r[0]), "=r"(r[1]), "=r"(r[2]), "=r"(r[3]) : "r"(addr));
}

// fp8 e4m3 MMA: m16n8k32, f32 accum (sm_89+ base ISA; full rate on sm_103a SIMT)
__device__ __forceinline__ void mma16832_fp8(float* c, const uint32_t* a, const uint32_t* b) {
    asm volatile(
        "mma.sync.aligned.m16n8k32.row.col.f32.e4m3.e4m3.f32 "
        "{%0,%1,%2,%3}, {%4,%5,%6,%7}, {%8,%9}, {%0,%1,%2,%3};"
        : "+f"(c[0]), "+f"(c[1]), "+f"(c[2]), "+f"(c[3])
        : "r"(a[0]), "r"(a[1]), "r"(a[2]), "r"(a[3]), "r"(b[0]), "r"(b[1]));
}

__device__ __forceinline__ uint32_t quad_to_fp8(float4 v) {
    __nv_fp8x2_storage_t lo = __nv_cvt_float2_to_fp8x2(make_float2(v.x, v.y),
                                                       __NV_SATFINITE, __NV_E4M3);
    __nv_fp8x2_storage_t hi = __nv_cvt_float2_to_fp8x2(make_float2(v.z, v.w),
                                                       __NV_SATFINITE, __NV_E4M3);
    return (uint32_t)lo | ((uint32_t)hi << 16);
}

// ---------------------------------------------------------------------------
// Fused prep: fp8 conversion (padded) + row squared norms.
// TWO adjacent rows per warp for 2x memory-level parallelism (latency-bound).
// Also zeroes the per-m-tile completion counters each launch.
// ---------------------------------------------------------------------------
__global__ __launch_bounds__(256)
void prep_kernel(const float* __restrict__ x,
                 const float* __restrict__ c,
                 const float* __restrict__ ls) {
    if (blockIdx.x == 0 && threadIdx.x < NMTILE) g_cnt[threadIdx.x] = 0;

    const int gw   = (blockIdx.x * blockDim.x + threadIdx.x) >> 5;  // warp id
    const int lane = threadIdx.x & 31;
    const int NPAIR = (B_ROWS + C_DIM) / 2;          // 9216
    if (gw >= NPAIR) return;

    const int r0   = gw * 2;                         // pair never straddles x/c
    const bool isX = r0 < B_ROWS;
    const int row0 = isX ? r0 : r0 - B_ROWS;

    const float4* s0 = (const float4*)((isX ? x : c) + (size_t)row0 * D_DIM);
    const float4* s1 = s0 + D_DIM / 4;               // row0+1 (contiguous)
    uint32_t* d0 = (isX ? g_xq : g_cq) + (size_t)row0 * KWORDS;
    uint32_t* d1 = d0 + KWORDS;

    float4 v0[7], v1[7];
    #pragma unroll
    for (int i = 0; i < 6; i++) { v0[i] = s0[lane + i * 32]; v1[i] = s1[lane + i * 32]; }
    const int wt = 192 + lane;
    v0[6] = (lane < 4) ? s0[wt] : make_float4(0.f, 0.f, 0.f, 0.f);
    v1[6] = (lane < 4) ? s1[wt] : make_float4(0.f, 0.f, 0.f, 0.f);

    float n0 = 0.f, n1 = 0.f;
    #pragma unroll
    for (int i = 0; i < 7; i++) {
        n0 = fmaf(v0[i].x, v0[i].x, fmaf(v0[i].y, v0[i].y,
             fmaf(v0[i].z, v0[i].z, fmaf(v0[i].w, v0[i].w, n0))));
        n1 = fmaf(v1[i].x, v1[i].x, fmaf(v1[i].y, v1[i].y,
             fmaf(v1[i].z, v1[i].z, fmaf(v1[i].w, v1[i].w, n1))));
    }

    #pragma unroll
    for (int i = 0; i < 6; i++) {
        d0[lane + i * 32] = quad_to_fp8(v0[i]);
        d1[lane + i * 32] = quad_to_fp8(v1[i]);
    }
    if (lane < 8) { d0[wt] = quad_to_fp8(v0[6]); d1[wt] = quad_to_fp8(v1[6]); }

    #pragma unroll
    for (int m = 16; m; m >>= 1) {
        n0 += __shfl_xor_sync(0xffffffffu, n0, m);
        n1 += __shfl_xor_sync(0xffffffffu, n1, m);
    }
    if (lane == 0) {
        if (isX) { g_x2[row0] = n0; g_x2[row0 + 1] = n1; }
        else {
            g_c2[row0]  = n0;  g_is2[row0]     = __expf(-2.f * ls[row0]);
            g_c2[row0 + 1] = n1; g_is2[row0 + 1] = __expf(-2.f * ls[row0 + 1]);
        }
    }
}

// ---------------------------------------------------------------------------
// Per-block address helper for the flattened persistent pipeline
// ---------------------------------------------------------------------------
struct BlkA { int m0, n0, koff, kb, cl, unit; };
__device__ __forceinline__ BlkA blk_addr(int gb, int cta, int stride) {
    BlkA b;
    const int ui  = gb / BPU;
    const int rem = gb - ui * BPU;
    b.cl   = rem / NKBLK;
    b.kb   = rem - b.cl * NKBLK;
    b.unit = cta + ui * stride;
    b.m0   = (b.unit >> 3) * TM;
    b.n0   = ((b.unit & (NSLICE - 1)) * CHPS + b.cl) * TN;
    b.koff = b.kb * KB;
    return b;
}

__device__ __forceinline__ void issue_tile(uint32_t sbase, int buf, const BlkA& b, int tid) {
    const uint32_t aOff = OFF_A + (uint32_t)buf * TILEB;
    const uint32_t bOff = OFF_B + (uint32_t)buf * TILEB;
    #pragma unroll
    for (int i = 0; i < 5; i++) {
        int idx = tid + i * NTHREADS;        // 0..1279
        int r = idx / 10, ch = idx - r * 10;
        cp16(sbase + aOff + (uint32_t)r * ASTB + ch * 16,
             (const char*)(g_xq + (size_t)(b.m0 + r) * KWORDS) + b.koff + ch * 16);
        cp16(sbase + bOff + (uint32_t)r * ASTB + ch * 16,
             (const char*)(g_cq + (size_t)(b.n0 + r) * KWORDS) + b.koff + ch * 16);
    }
    CP_COMMIT();
}

// ---------------------------------------------------------------------------
// Persistent main kernel: fp8 mma, 3-stage continuous cp.async pipeline,
// register epilogue with exact underflow skip, fused final reduction
// (last CTA to finish an m-tile's 8 slices sums partials + bias -> out).
// ---------------------------------------------------------------------------
__global__ __launch_bounds__(NTHREADS, 1)
void rbf_mma_kernel(const float* __restrict__ W,
                    const float* __restrict__ bias,
                    float* __restrict__ out) {
    extern __shared__ char sm[];
    const uint32_t sbase = smem_u32(sm);
    __shared__ int s_last;

    const int tid  = threadIdx.x;
    const int wid  = tid >> 5;
    const int lane = tid & 31;
    const int wm   = wid & 3;
    const int wn   = wid >> 2;
    const int lm   = lane >> 2;
    const int ln   = (lane & 3) * 2;
    const int cta  = blockIdx.x;
    const int strd = gridDim.x;

    float* c2S   = (float*)(sm + OFF_C2);
    float* is2S  = (float*)(sm + OFF_IS2);
    float* WcolS = (float*)(sm + OFF_WCOL);
    float* redS  = (float*)(sm + OFF_RED);

    const int n_units = (NUNITS - cta + strd - 1) / strd;
    const int NB = n_units * BPU;
    if (n_units <= 0) return;

    issue_tile(sbase, 0, blk_addr(0, cta, strd), tid);
    if (NB > 1) issue_tile(sbase, 1, blk_addr(1, cta, strd), tid);

    float oacc[4][OUT_DIM];
    #pragma unroll
    for (int i = 0; i < 4; i++)
        #pragma unroll
        for (int o = 0; o < OUT_DIM; o++) oacc[i][o] = 0.f;

    float acc[2][8][4];
    float x2a0 = 0.f, x2b0 = 0.f, x2a1 = 0.f, x2b1 = 0.f;

    for (int gb = 0; gb < NB; gb++) {
        const BlkA b = blk_addr(gb, cta, strd);
        const int buf = gb % NSTAGE;

        if (b.kb == 0) {
            if (b.cl == 0) {
                const int ra0 = b.m0 + wm * 32 + lm;
                x2a0 = g_x2[ra0];      x2b0 = g_x2[ra0 + 8];
                x2a1 = g_x2[ra0 + 16]; x2b1 = g_x2[ra0 + 24];
            }
            if (tid < TN) {
                c2S[tid]  = g_c2[b.n0 + tid];
                is2S[tid] = g_is2[b.n0 + tid];
            }
            #pragma unroll
            for (int i = 0; i < 5; i++) {
                int idx = tid + i * NTHREADS;      // TN*OUT = 1280
                int cc = idx / OUT_DIM, o = idx - cc * OUT_DIM;
                WcolS[cc * WST + o] = W[(size_t)o * C_DIM + b.n0 + cc];
            }
            #pragma unroll
            for (int i = 0; i < 2; i++)
                #pragma unroll
                for (int j = 0; j < 8; j++)
                    #pragma unroll
                    for (int e = 0; e < 4; e++) acc[i][j][e] = 0.f;
        }

        if (gb + 1 < NB) CP_WAIT1(); else CP_WAIT0();
        __syncthreads();   // tile + metadata visible CTA-wide

        if (gb + 2 < NB)
            issue_tile(sbase, (gb + 2) % NSTAGE, blk_addr(gb + 2, cta, strd), tid);

        const uint32_t aBase = sbase + OFF_A + (uint32_t)buf * TILEB;
        const uint32_t bBase = sbase + OFF_B + (uint32_t)buf * TILEB;
        const uint32_t lrow  = (uint32_t)(lane & 15);
        const uint32_t lcol  = (uint32_t)(lane >> 4) * 16u;

        #pragma unroll
        for (int ks = 0; ks < NK32; ks++) {
            uint32_t af[2][4];
            #pragma unroll
            for (int mi = 0; mi < 2; mi++)
                ldm_x4(af[mi], aBase + (uint32_t)(wm * 32 + mi * 16 + lrow) * ASTB
                                     + (uint32_t)ks * 32u + lcol);
            uint32_t bf[8][2];
            #pragma unroll
            for (int njj = 0; njj < 4; njj++) {
                uint32_t r4[4];
                ldm_x4(r4, bBase + (uint32_t)(wn * 64 + njj * 16 + lrow) * ASTB
                                 + (uint32_t)ks * 32u + lcol);
                bf[njj * 2 + 0][0] = r4[0];
                bf[njj * 2 + 1][0] = r4[1];
                bf[njj * 2 + 0][1] = r4[2];
                bf[njj * 2 + 1][1] = r4[3];
            }
            #pragma unroll
            for (int mi = 0; mi < 2; mi++)
                #pragma unroll
                for (int nf = 0; nf < 8; nf++)
                    mma16832_fp8(acc[mi][nf], af[mi], bf[nf]);
        }

        if (b.kb == NKBLK - 1) {
            // ---- chunk epilogue: t = d2*is2; exp(-t)==0 exactly for t>104 ----
            #pragma unroll
            for (int nf = 0; nf < 8; nf++) {
                const int c0 = wn * 64 + nf * 8 + ln;
                const int c1 = c0 + 1;
                const float cc0 = c2S[c0],  cc1 = c2S[c1];
                const float ii0 = is2S[c0], ii1 = is2S[c1];
                #pragma unroll
                for (int mi = 0; mi < 2; mi++) {
                    const float xa = mi ? x2a1 : x2a0;
                    const float xb = mi ? x2b1 : x2b0;
                    const float t00 = fmaxf(xa + cc0 - 2.f * acc[mi][nf][0], 0.f) * ii0;
                    const float t01 = fmaxf(xa + cc1 - 2.f * acc[mi][nf][1], 0.f) * ii1;
                    const float t10 = fmaxf(xb + cc0 - 2.f * acc[mi][nf][2], 0.f) * ii0;
                    const float t11 = fmaxf(xb + cc1 - 2.f * acc[mi][nf][3], 0.f) * ii1;
                    if (t00 < 104.f || t01 < 104.f || t10 < 104.f || t11 < 104.f) {
                        const float p00 = __expf(-t00);
                        const float p01 = __expf(-t01);
                        const float p10 = __expf(-t10);
                        const float p11 = __expf(-t11);
                        #pragma unroll
                        for (int o = 0; o < OUT_DIM; o++) {
                            const float w0 = WcolS[c0 * WST + o];
                            const float w1 = WcolS[c1 * WST + o];
                            oacc[mi * 2 + 0][o] = fmaf(p00, w0, fmaf(p01, w1, oacc[mi * 2 + 0][o]));
                            oacc[mi * 2 + 1][o] = fmaf(p10, w0, fmaf(p11, w1, oacc[mi * 2 + 1][o]));
                        }
                    }
                }
            }
            __syncthreads();   // meta consumed; next chunk may overwrite

            if (b.cl == CHPS - 1) {
                // ---- unit-end: cross-lane + cross-warp reduce, write partial ----
                #pragma unroll
                for (int i = 0; i < 4; i++)
                    #pragma unroll
                    for (int o = 0; o < OUT_DIM; o++) {
                        float v = oacc[i][o];
                        v += __shfl_xor_sync(0xffffffffu, v, 1);
                        v += __shfl_xor_sync(0xffffffffu, v, 2);
                        oacc[i][o] = v;
                    }
                if (wn == 0 && (lane & 3) == 0) {
                    #pragma unroll
                    for (int i = 0; i < 4; i++) {
                        const int r = wm * 32 + (i >> 1) * 16 + (i & 1) * 8 + lm;
                        #pragma unroll
                        for (int o = 0; o < OUT_DIM; o++) redS[r * WST + o] = oacc[i][o];
                    }
                }
                __syncthreads();
                if (wn == 1 && (lane & 3) == 0) {
                    #pragma unroll
                    for (int i = 0; i < 4; i++) {
                        const int r = wm * 32 + (i >> 1) * 16 + (i & 1) * 8 + lm;
                        #pragma unroll
                        for (int o = 0; o < OUT_DIM; o++) redS[r * WST + o] += oacc[i][o];
                    }
                }
                __syncthreads();

                const int slice = b.unit & (NSLICE - 1);
                const int mt    = b.unit >> 3;
                float* pbase = g_part + (size_t)slice * B_ROWS * OUT_DIM
                             + (size_t)b.m0 * OUT_DIM;
                #pragma unroll
                for (int i = 0; i < 5; i++) {
                    const int e = tid + i * NTHREADS;
                    pbase[e] = redS[(e / OUT_DIM) * WST + (e - (e / OUT_DIM) * OUT_DIM)];
                }
                #pragma unroll
                for (int i = 0; i < 4; i++)
                    #pragma unroll
                    for (int o = 0; o < OUT_DIM; o++) oacc[i][o] = 0.f;

                // ---- fused final reduction: last slice of this m-tile sums all ----
                __threadfence();                       // release partial writes
                if (tid == 0)
                    s_last = (atomicAdd(&g_cnt[mt], 1) == NSLICE - 1);
                __syncthreads();
                if (s_last) {
                    __threadfence();                   // acquire others' partials
                    #pragma unroll
                    for (int i = 0; i < 5; i++) {
                        const int e = tid + i * NTHREADS;   // 0..1279
                        const int o = e - (e / OUT_DIM) * OUT_DIM;
                        float v = __ldg(&bias[o]);
                        #pragma unroll
                        for (int sl = 0; sl < NSLICE; sl++)
                            v += g_part[(size_t)sl * B_ROWS * OUT_DIM
                                        + (size_t)b.m0 * OUT_DIM + e];
                        out[(size_t)b.m0 * OUT_DIM + e] = v;
                    }
                }
                __syncthreads();   // redS/s_last consumed before next unit
            }
        }
    }
}

// ---------------------------------------------------------------------------
// Launch
// ---------------------------------------------------------------------------
extern "C" void kernel_launch(void* const* d_in, const int* in_sizes, int n_in,
                              void* d_out, int out_size) {
    const float* x       = (const float*)d_in[0];
    const float* centres = (const float*)d_in[1];
    const float* ls      = (const float*)d_in[2];
    const float* W       = (const float*)d_in[3];
    const float* bias    = (const float*)d_in[4];
    float* out           = (float*)d_out;

    int nsm = 148;
    cudaDeviceGetAttribute(&nsm, cudaDevAttrMultiProcessorCount, 0);

    const int npairs = (B_ROWS + C_DIM) / 2;        // 9216 warp work items
    prep_kernel<<<(npairs + 7) / 8, 256>>>(x, centres, ls);

    cudaFuncSetAttribute(rbf_mma_kernel,
                         cudaFuncAttributeMaxDynamicSharedMemorySize, SMEM_TOTAL);
    rbf_mma_kernel<<<nsm, NTHREADS, SMEM_TOTAL>>>(W, bias, out);
}

// round 11
// speedup vs baseline: 1.0366x; 1.0366x over previous
#include <cuda_runtime.h>
#include <cuda_fp8.h>
#include <cstdint>

// ---------------------------------------------------------------------------
// Problem constants
// ---------------------------------------------------------------------------
#define B_ROWS  16384
#define D_DIM   784
#define C_DIM   2048
#define OUT_DIM 10

#define KPAD   800               // 784 padded to 25*32 (fp8 bytes)
#define KWORDS 200               // KPAD/4
#define ROWB   800               // bytes per row
#define KB     160               // K bytes per pipeline block
#define NKBLK  5                 // blocks per chunk (5*160 = 800)
#define NK32   5                 // k32 steps per block
#define TM     128               // x rows per unit
#define TN     128               // centres per chunk
#define NSLICE 8                 // C split across units
#define CHPS   2                 // chunks per unit (256 centres)
#define BPU    (CHPS * NKBLK)    // 10 blocks per unit
#define NUNITS ((B_ROWS / TM) * NSLICE)   // 1024 work units
#define NTHREADS 256

// smem tile stride: 160 data + 16 pad bytes (ldmatrix phases r*11 mod 8 distinct)
#define ASTB  176
#define TILEB 22528u             // 128 * 176
#define NSTAGE 4
#define WST   12                 // floats per Wcol row (10 + 2 pad)

// smem byte offsets
#define OFF_A    0u                       // 4 x 22528 = 90112
#define OFF_B    90112u                   // 4 x 22528 = 90112
#define OFF_WCOL 180224u                  // 128 x 12 x 4 = 6144
#define OFF_C2   186368u                  // 128 x 4
#define OFF_IS2  186880u
#define OFF_RED  187392u                  // 128 x 12 x 4 = 6144
#define SMEM_TOTAL 193536u

// ---------------------------------------------------------------------------
// Device-global scratch (no allocations allowed)
// ---------------------------------------------------------------------------
__device__ __align__(16) uint32_t g_xq[(size_t)B_ROWS * KWORDS];   // 13.1 MB fp8
__device__ __align__(16) uint32_t g_cq[(size_t)C_DIM * KWORDS];    // 1.6 MB fp8
__device__ float g_x2[B_ROWS];
__device__ float g_c2[C_DIM];
__device__ float g_is2[C_DIM];
__device__ __align__(16) float g_part[(size_t)NSLICE * B_ROWS * OUT_DIM]; // 5.2 MB

// ---------------------------------------------------------------------------
// PTX helpers (base-ISA sm_80/89 era; valid for compute_103 virtual arch)
// ---------------------------------------------------------------------------
__device__ __forceinline__ uint32_t smem_u32(const void* p) {
    uint32_t a;
    asm("{ .reg .u64 t; cvta.to.shared.u64 t, %1; cvt.u32.u64 %0, t; }" : "=r"(a) : "l"(p));
    return a;
}

__device__ __forceinline__ void cp16(uint32_t dst, const void* src) {
    asm volatile("cp.async.cg.shared.global [%0], [%1], 16;" :: "r"(dst), "l"(src));
}
#define CP_COMMIT() asm volatile("cp.async.commit_group;" ::: "memory")
#define CP_WAIT0()  asm volatile("cp.async.wait_group 0;"  ::: "memory")
#define CP_WAIT1()  asm volatile("cp.async.wait_group 1;"  ::: "memory")
#define CP_WAIT2()  asm volatile("cp.async.wait_group 2;"  ::: "memory")

__device__ __forceinline__ void ldm_x4(uint32_t* r, uint32_t addr) {
    asm volatile("ldmatrix.sync.aligned.m8n8.x4.shared.b16 {%0,%1,%2,%3}, [%4];"
                 : "=r"(r[0]), "=r"(r[1]), "=r"(r[2]), "=r"(r[3]) : "r"(addr));
}

// fp8 e4m3 MMA: m16n8k32, f32 accum (sm_89+ base ISA)
__device__ __forceinline__ void mma16832_fp8(float* c, const uint32_t* a, const uint32_t* b) {
    asm volatile(
        "mma.sync.aligned.m16n8k32.row.col.f32.e4m3.e4m3.f32 "
        "{%0,%1,%2,%3}, {%4,%5,%6,%7}, {%8,%9}, {%0,%1,%2,%3};"
        : "+f"(c[0]), "+f"(c[1]), "+f"(c[2]), "+f"(c[3])
        : "r"(a[0]), "r"(a[1]), "r"(a[2]), "r"(a[3]), "r"(b[0]), "r"(b[1]));
}

__device__ __forceinline__ uint32_t quad_to_fp8(float4 v) {
    __nv_fp8x2_storage_t lo = __nv_cvt_float2_to_fp8x2(make_float2(v.x, v.y),
                                                       __NV_SATFINITE, __NV_E4M3);
    __nv_fp8x2_storage_t hi = __nv_cvt_float2_to_fp8x2(make_float2(v.z, v.w),
                                                       __NV_SATFINITE, __NV_E4M3);
    return (uint32_t)lo | ((uint32_t)hi << 16);
}

// ---------------------------------------------------------------------------
// Fused prep: fp8 conversion (padded) + row squared norms.
// Two adjacent rows per warp for 2x memory-level parallelism.
// ---------------------------------------------------------------------------
__global__ __launch_bounds__(256)
void prep_kernel(const float* __restrict__ x,
                 const float* __restrict__ c,
                 const float* __restrict__ ls) {
    const int gw   = (blockIdx.x * blockDim.x + threadIdx.x) >> 5;
    const int lane = threadIdx.x & 31;
    const int NPAIR = (B_ROWS + C_DIM) / 2;          // 9216
    if (gw >= NPAIR) return;

    const int r0   = gw * 2;
    const bool isX = r0 < B_ROWS;
    const int row0 = isX ? r0 : r0 - B_ROWS;

    const float4* s0 = (const float4*)((isX ? x : c) + (size_t)row0 * D_DIM);
    const float4* s1 = s0 + D_DIM / 4;
    uint32_t* d0 = (isX ? g_xq : g_cq) + (size_t)row0 * KWORDS;
    uint32_t* d1 = d0 + KWORDS;

    float4 v0[7], v1[7];
    #pragma unroll
    for (int i = 0; i < 6; i++) { v0[i] = s0[lane + i * 32]; v1[i] = s1[lane + i * 32]; }
    const int wt = 192 + lane;
    v0[6] = (lane < 4) ? s0[wt] : make_float4(0.f, 0.f, 0.f, 0.f);
    v1[6] = (lane < 4) ? s1[wt] : make_float4(0.f, 0.f, 0.f, 0.f);

    float n0 = 0.f, n1 = 0.f;
    #pragma unroll
    for (int i = 0; i < 7; i++) {
        n0 = fmaf(v0[i].x, v0[i].x, fmaf(v0[i].y, v0[i].y,
             fmaf(v0[i].z, v0[i].z, fmaf(v0[i].w, v0[i].w, n0))));
        n1 = fmaf(v1[i].x, v1[i].x, fmaf(v1[i].y, v1[i].y,
             fmaf(v1[i].z, v1[i].z, fmaf(v1[i].w, v1[i].w, n1))));
    }

    #pragma unroll
    for (int i = 0; i < 6; i++) {
        d0[lane + i * 32] = quad_to_fp8(v0[i]);
        d1[lane + i * 32] = quad_to_fp8(v1[i]);
    }
    if (lane < 8) { d0[wt] = quad_to_fp8(v0[6]); d1[wt] = quad_to_fp8(v1[6]); }

    #pragma unroll
    for (int m = 16; m; m >>= 1) {
        n0 += __shfl_xor_sync(0xffffffffu, n0, m);
        n1 += __shfl_xor_sync(0xffffffffu, n1, m);
    }
    if (lane == 0) {
        if (isX) { g_x2[row0] = n0; g_x2[row0 + 1] = n1; }
        else {
            g_c2[row0]     = n0; g_is2[row0]     = __expf(-2.f * ls[row0]);
            g_c2[row0 + 1] = n1; g_is2[row0 + 1] = __expf(-2.f * ls[row0 + 1]);
        }
    }
}

// ---------------------------------------------------------------------------
// Incrementally-advanced block state: no divisions in the hot path.
// ---------------------------------------------------------------------------
struct St { int kb, cl, unit, m0, n0, koff; };

__device__ __forceinline__ void st_init(St& s, int cta) {
    s.kb = 0; s.cl = 0; s.unit = cta; s.koff = 0;
    s.m0 = (cta >> 3) * TM;
    s.n0 = (cta & (NSLICE - 1)) * (CHPS * TN);
}

__device__ __forceinline__ void st_adv(St& s, int strd) {
    s.kb++; s.koff += KB;
    if (s.kb == NKBLK) {
        s.kb = 0; s.koff = 0; s.n0 += TN;
        if (++s.cl == CHPS) {
            s.cl = 0; s.unit += strd;
            s.m0 = (s.unit >> 3) * TM;
            s.n0 = (s.unit & (NSLICE - 1)) * (CHPS * TN);
        }
    }
}

// ---------------------------------------------------------------------------
// Persistent main kernel: fp8 mma, 4-stage continuous cp.async pipeline,
// division-free hot path, hoisted per-thread copy offsets,
// register epilogue with exact underflow skip.
// ---------------------------------------------------------------------------
__global__ __launch_bounds__(NTHREADS, 1)
void rbf_mma_kernel(const float* __restrict__ W) {
    extern __shared__ char sm[];
    const uint32_t sbase = smem_u32(sm);

    const int tid  = threadIdx.x;
    const int wid  = tid >> 5;
    const int lane = tid & 31;
    const int wm   = wid & 3;
    const int wn   = wid >> 2;
    const int lm   = lane >> 2;
    const int ln   = (lane & 3) * 2;
    const int cta  = blockIdx.x;
    const int strd = gridDim.x;

    float* c2S   = (float*)(sm + OFF_C2);
    float* is2S  = (float*)(sm + OFF_IS2);
    float* WcolS = (float*)(sm + OFF_WCOL);
    float* redS  = (float*)(sm + OFF_RED);

    const int n_units = (NUNITS - cta + strd - 1) / strd;
    if (n_units <= 0) return;
    const int NB = n_units * BPU;

    // hoisted per-thread copy offsets (divisions done exactly once)
    uint32_t so[5], go[5];
    #pragma unroll
    for (int i = 0; i < 5; i++) {
        const int idx = tid + i * NTHREADS;
        const int r = idx / 10, ch = idx - r * 10;
        so[i] = (uint32_t)(r * ASTB + ch * 16);
        go[i] = (uint32_t)(r * ROWB + ch * 16);
    }
    // hoisted per-warp ldmatrix row offsets
    const uint32_t lrow  = (uint32_t)(lane & 15);
    const uint32_t lcol  = (uint32_t)(lane >> 4) * 16u;
    const uint32_t aoff0 = (uint32_t)(wm * 32 + lrow) * ASTB + lcol;
    const uint32_t aoff1 = aoff0 + 16u * ASTB;
    uint32_t boff[4];
    #pragma unroll
    for (int j = 0; j < 4; j++)
        boff[j] = (uint32_t)(wn * 64 + j * 16 + lrow) * ASTB + lcol;

    // prologue: 3 tiles in flight
    St pf; st_init(pf, cta);
    #pragma unroll
    for (int p = 0; p < NSTAGE - 1; p++) {
        const char* xb = (const char*)g_xq + (size_t)pf.m0 * ROWB + pf.koff;
        const char* cb = (const char*)g_cq + (size_t)pf.n0 * ROWB + pf.koff;
        const uint32_t aO = sbase + OFF_A + (uint32_t)p * TILEB;
        const uint32_t bO = sbase + OFF_B + (uint32_t)p * TILEB;
        #pragma unroll
        for (int i = 0; i < 5; i++) { cp16(aO + so[i], xb + go[i]); cp16(bO + so[i], cb + go[i]); }
        CP_COMMIT();
        st_adv(pf, strd);
    }

    float oacc[4][OUT_DIM];
    #pragma unroll
    for (int i = 0; i < 4; i++)
        #pragma unroll
        for (int o = 0; o < OUT_DIM; o++) oacc[i][o] = 0.f;

    float acc[2][8][4];
    float x2a0 = 0.f, x2b0 = 0.f, x2a1 = 0.f, x2b1 = 0.f;

    St cur; st_init(cur, cta);
    int buf = 0, pbuf = NSTAGE - 1;

    for (int gb = 0; gb < NB; gb++) {
        if (cur.kb == 0) {
            if (cur.cl == 0) {
                const int ra0 = cur.m0 + wm * 32 + lm;
                x2a0 = g_x2[ra0];      x2b0 = g_x2[ra0 + 8];
                x2a1 = g_x2[ra0 + 16]; x2b1 = g_x2[ra0 + 24];
            }
            if (tid < TN) {
                c2S[tid]  = g_c2[cur.n0 + tid];
                is2S[tid] = g_is2[cur.n0 + tid];
            }
            #pragma unroll
            for (int i = 0; i < 5; i++) {
                const int idx = tid + i * NTHREADS;
                const int cc = idx / 10, o = idx - cc * 10;   // cold path (per chunk)
                WcolS[cc * WST + o] = W[(size_t)o * C_DIM + cur.n0 + cc];
            }
            #pragma unroll
            for (int i = 0; i < 2; i++)
                #pragma unroll
                for (int j = 0; j < 8; j++)
                    #pragma unroll
                    for (int e = 0; e < 4; e++) acc[i][j][e] = 0.f;
        }

        {   // wait for tile gb (pending allowed = min(2, NB-1-gb))
            const int rem = NB - 1 - gb;
            if (rem >= 2) CP_WAIT2();
            else if (rem == 1) CP_WAIT1();
            else CP_WAIT0();
        }
        __syncthreads();   // tile + metadata visible CTA-wide

        // prefetch tile gb+3
        if (gb + NSTAGE - 1 < NB) {
            const char* xb = (const char*)g_xq + (size_t)pf.m0 * ROWB + pf.koff;
            const char* cb = (const char*)g_cq + (size_t)pf.n0 * ROWB + pf.koff;
            const uint32_t aO = sbase + OFF_A + (uint32_t)pbuf * TILEB;
            const uint32_t bO = sbase + OFF_B + (uint32_t)pbuf * TILEB;
            #pragma unroll
            for (int i = 0; i < 5; i++) { cp16(aO + so[i], xb + go[i]); cp16(bO + so[i], cb + go[i]); }
            CP_COMMIT();
            st_adv(pf, strd);
            if (++pbuf == NSTAGE) pbuf = 0;
        }

        const uint32_t aBase = sbase + OFF_A + (uint32_t)buf * TILEB;
        const uint32_t bBase = sbase + OFF_B + (uint32_t)buf * TILEB;

        #pragma unroll
        for (int ks = 0; ks < NK32; ks++) {
            uint32_t af[2][4];
            ldm_x4(af[0], aBase + aoff0 + (uint32_t)ks * 32u);
            ldm_x4(af[1], aBase + aoff1 + (uint32_t)ks * 32u);
            uint32_t bf[8][2];
            #pragma unroll
            for (int njj = 0; njj < 4; njj++) {
                uint32_t r4[4];
                ldm_x4(r4, bBase + boff[njj] + (uint32_t)ks * 32u);
                bf[njj * 2 + 0][0] = r4[0];
                bf[njj * 2 + 1][0] = r4[1];
                bf[njj * 2 + 0][1] = r4[2];
                bf[njj * 2 + 1][1] = r4[3];
            }
            #pragma unroll
            for (int mi = 0; mi < 2; mi++)
                #pragma unroll
                for (int nf = 0; nf < 8; nf++)
                    mma16832_fp8(acc[mi][nf], af[mi], bf[nf]);
        }

        if (cur.kb == NKBLK - 1) {
            // ---- chunk epilogue: t = d2*is2; exp(-t)==0 exactly for t>104 ----
            #pragma unroll
            for (int nf = 0; nf < 8; nf++) {
                const int c0 = wn * 64 + nf * 8 + ln;
                const int c1 = c0 + 1;
                const float cc0 = c2S[c0],  cc1 = c2S[c1];
                const float ii0 = is2S[c0], ii1 = is2S[c1];
                #pragma unroll
                for (int mi = 0; mi < 2; mi++) {
                    const float xa = mi ? x2a1 : x2a0;
                    const float xb = mi ? x2b1 : x2b0;
                    const float t00 = fmaxf(xa + cc0 - 2.f * acc[mi][nf][0], 0.f) * ii0;
                    const float t01 = fmaxf(xa + cc1 - 2.f * acc[mi][nf][1], 0.f) * ii1;
                    const float t10 = fmaxf(xb + cc0 - 2.f * acc[mi][nf][2], 0.f) * ii0;
                    const float t11 = fmaxf(xb + cc1 - 2.f * acc[mi][nf][3], 0.f) * ii1;
                    if (t00 < 104.f || t01 < 104.f || t10 < 104.f || t11 < 104.f) {
                        const float p00 = __expf(-t00);
                        const float p01 = __expf(-t01);
                        const float p10 = __expf(-t10);
                        const float p11 = __expf(-t11);
                        #pragma unroll
                        for (int o = 0; o < OUT_DIM; o++) {
                            const float w0 = WcolS[c0 * WST + o];
                            const float w1 = WcolS[c1 * WST + o];
                            oacc[mi * 2 + 0][o] = fmaf(p00, w0, fmaf(p01, w1, oacc[mi * 2 + 0][o]));
                            oacc[mi * 2 + 1][o] = fmaf(p10, w0, fmaf(p11, w1, oacc[mi * 2 + 1][o]));
                        }
                    }
                }
            }
            __syncthreads();   // meta consumed; next chunk may overwrite

            if (cur.cl == CHPS - 1) {
                // ---- unit-end: cross-lane + cross-warp reduce, write partial ----
                #pragma unroll
                for (int i = 0; i < 4; i++)
                    #pragma unroll
                    for (int o = 0; o < OUT_DIM; o++) {
                        float v = oacc[i][o];
                        v += __shfl_xor_sync(0xffffffffu, v, 1);
                        v += __shfl_xor_sync(0xffffffffu, v, 2);
                        oacc[i][o] = v;
                    }
                if (wn == 0 && (lane & 3) == 0) {
                    #pragma unroll
                    for (int i = 0; i < 4; i++) {
                        const int r = wm * 32 + (i >> 1) * 16 + (i & 1) * 8 + lm;
                        #pragma unroll
                        for (int o = 0; o < OUT_DIM; o++) redS[r * WST + o] = oacc[i][o];
                    }
                }
                __syncthreads();
                if (wn == 1 && (lane & 3) == 0) {
                    #pragma unroll
                    for (int i = 0; i < 4; i++) {
                        const int r = wm * 32 + (i >> 1) * 16 + (i & 1) * 8 + lm;
                        #pragma unroll
                        for (int o = 0; o < OUT_DIM; o++) redS[r * WST + o] += oacc[i][o];
                    }
                }
                __syncthreads();

                const int slice = cur.unit & (NSLICE - 1);
                float* pbase = g_part + (size_t)slice * B_ROWS * OUT_DIM
                             + (size_t)cur.m0 * OUT_DIM;
                #pragma unroll
                for (int i = 0; i < 5; i++) {
                    const int e = tid + i * NTHREADS;
                    const int r = e / 10, o = e - r * 10;      // cold path (per unit)
                    pbase[e] = redS[r * WST + o];
                }
                #pragma unroll
                for (int i = 0; i < 4; i++)
                    #pragma unroll
                    for (int o = 0; o < OUT_DIM; o++) oacc[i][o] = 0.f;
                __syncthreads();   // redS consumed before next unit reuses it
            }
        }

        st_adv(cur, strd);
        if (++buf == NSTAGE) buf = 0;
    }
}

// ---------------------------------------------------------------------------
// Reduce: out = sum of 8 slice partials + bias  (float4 vectorized)
// ---------------------------------------------------------------------------
__global__ void reduce_kernel(const float* __restrict__ bias, float* __restrict__ out) {
    const int t = blockIdx.x * blockDim.x + threadIdx.x;       // float4 index
    const int NQ = (B_ROWS * OUT_DIM) / 4;                     // 40960
    if (t >= NQ) return;
    const int i0 = t * 4;
    float4 s;
    s.x = __ldg(&bias[(i0 + 0) % OUT_DIM]);
    s.y = __ldg(&bias[(i0 + 1) % OUT_DIM]);
    s.z = __ldg(&bias[(i0 + 2) % OUT_DIM]);
    s.w = __ldg(&bias[(i0 + 3) % OUT_DIM]);
    #pragma unroll
    for (int sl = 0; sl < NSLICE; sl++) {
        const float4 p = *(const float4*)&g_part[(size_t)sl * B_ROWS * OUT_DIM + i0];
        s.x += p.x; s.y += p.y; s.z += p.z; s.w += p.w;
    }
    ((float4*)out)[t] = s;
}

// ---------------------------------------------------------------------------
// Launch
// ---------------------------------------------------------------------------
extern "C" void kernel_launch(void* const* d_in, const int* in_sizes, int n_in,
                              void* d_out, int out_size) {
    const float* x       = (const float*)d_in[0];
    const float* centres = (const float*)d_in[1];
    const float* ls      = (const float*)d_in[2];
    const float* W       = (const float*)d_in[3];
    const float* bias    = (const float*)d_in[4];
    float* out           = (float*)d_out;

    int nsm = 148;
    cudaDeviceGetAttribute(&nsm, cudaDevAttrMultiProcessorCount, 0);

    const int npairs = (B_ROWS + C_DIM) / 2;        // 9216 warp work items
    prep_kernel<<<(npairs + 7) / 8, 256>>>(x, centres, ls);

    cudaFuncSetAttribute(rbf_mma_kernel,
                         cudaFuncAttributeMaxDynamicSharedMemorySize, SMEM_TOTAL);
    rbf_mma_kernel<<<nsm, NTHREADS, SMEM_TOTAL>>>(W);

    reduce_kernel<<<((B_ROWS * OUT_DIM) / 4 + 255) / 256, 256>>>(bias, out);
}